// round 13
// baseline (speedup 1.0000x reference)
#include <cuda_runtime.h>
#include <cuda_fp16.h>

// LSTM B=2048, T=512, LATENT=18, HID=32, gates (i,f,g,o), 4H=128.
// R13 = R12 (register-pointwise fused TC kernel) with the z-staging coverage
// bug fixed: 144 staging slots (16 rows x 9 pairs) on a 128-thread block now
// handled as 2 slots/thread (R12's `tid<144` left rows 14-15 with z=0).
// 128 blocks x 128 threads (4 warps). Warp w owns n8-tiles at cols 32g+8w
// for all four gate blocks -> each thread's accumulators hold the full
// (i,f,g,o) quadruple for hidden j0=8w+2tc,+1 on rows gr,gr+8: pointwise in
// registers, no C smem, ONE __syncthreads per step (double-buffered A).
// Proj tiles on warps 0..2 emit z_pred from registers. Residual-split fp16.

#define NB 2048
#define NT 512
#define NL 18
#define NH 32
#define KS 12          // k-steps of 16 (K=192)
#define ASTR 200       // half stride of A rows

typedef unsigned int u32;

__device__ __forceinline__ float ex2(float x) {
    float r; asm("ex2.approx.f32 %0,%1;" : "=f"(r) : "f"(x)); return r;
}
__device__ __forceinline__ float rcpa(float x) {
    float r; asm("rcp.approx.f32 %0,%1;" : "=f"(r) : "f"(x)); return r;
}
__device__ __forceinline__ float sigmoid_fast(float x) {
    return rcpa(1.0f + ex2(-1.4426950408889634f * x));
}
__device__ __forceinline__ float tanh_fast(float x) {
    return 1.0f - 2.0f * rcpa(ex2(2.8853900817779268f * x) + 1.0f);
}

__device__ __forceinline__ u32 h2u32(__half a, __half b) {
    __half2 hv = __halves2half2(a, b);
    return *reinterpret_cast<u32*>(&hv);
}

__device__ __forceinline__ void mma16816(float d[4], const u32 a[4], const u32 b[2]) {
    asm volatile(
        "mma.sync.aligned.m16n8k16.row.col.f32.f16.f16.f32 "
        "{%0,%1,%2,%3}, {%4,%5,%6,%7}, {%8,%9}, {%0,%1,%2,%3};"
        : "+f"(d[0]), "+f"(d[1]), "+f"(d[2]), "+f"(d[3])
        : "r"(a[0]), "r"(a[1]), "r"(a[2]), "r"(a[3]), "r"(b[0]), "r"(b[1]));
}

// Gate B_eff[kk][n], n = gate row 0..127 (main part kk<128, residual kk>=128)
__device__ __forceinline__ __half w16eff(const float* Whh, const float* Wih,
                                         int n, int kk) {
    float w;
    bool res = false;
    if (kk < 32)        w = Whh[n * NH + kk];
    else if (kk < 64)   w = Whh[n * NH + (kk - 32)];
    else if (kk < 96)   { int c = kk - 64; w = (c < NL) ? Wih[n * NL + c] : 0.f; }
    else if (kk < 128)  { int c = kk - 96; w = (c < NL) ? Wih[n * NL + c] : 0.f; }
    else if (kk < 160)  { w = Whh[n * NH + (kk - 128)]; res = true; }
    else                { int c = kk - 160; w = (c < NL) ? Wih[n * NL + c] : 0.f; res = true; }
    __half h = __float2half_rn(w);
    if (!res) return h;
    return __float2half_rn(w - __half2float(h));
}

// Projection B_eff[kk][m]: kk0-31 Wout16 (vs h16), kk32-63 Wout16 (vs hr),
// kk128-159 Wres (vs h16), else 0.
__device__ __forceinline__ __half wout_eff(const float* Wout, int m, int kk) {
    if (m >= NL) return __float2half_rn(0.f);
    float w; bool res = false;
    if (kk < 32)        w = Wout[m * NH + kk];
    else if (kk < 64)   w = Wout[m * NH + (kk - 32)];
    else if (kk < 128)  return __float2half_rn(0.f);
    else if (kk < 160)  { w = Wout[m * NH + (kk - 128)]; res = true; }
    else                return __float2half_rn(0.f);
    __half h = __float2half_rn(w);
    if (!res) return h;
    return __float2half_rn(w - __half2float(h));
}

__global__ __launch_bounds__(128, 1)
void lstm_fused_tc(const float* __restrict__ z,
                   const float* __restrict__ Wih,
                   const float* __restrict__ Whh,
                   const float* __restrict__ bih,
                   const float* __restrict__ bhh,
                   const float* __restrict__ Wout,
                   const float* __restrict__ bout,
                   float* __restrict__ out)
{
    // double-buffered A: kk 0-31 h16, 32-63 hr, 64-95 z16, 96-127 zr,
    //                    128-159 h16, 160-191 z16
    __shared__ __half As[2][16][ASTR];

    const int tid  = threadIdx.x;
    const int warp = tid >> 5;        // 0..3
    const int lane = tid & 31;
    const int gr   = lane >> 2;       // 0..7
    const int tc   = lane & 3;        // 0..3
    const int be   = blockIdx.x * 16;
    const int j0   = 8 * warp + 2 * tc;   // this thread's hidden pair

    // ---- gate B fragments: 4 tiles (one per gate block), cols 32g+8w+gr ----
    u32 Bf[4][KS][2];
    #pragma unroll
    for (int g = 0; g < 4; g++) {
        int n = 32 * g + 8 * warp + gr;
        #pragma unroll
        for (int s = 0; s < KS; s++) {
            int k0 = 16 * s + 2 * tc;
            Bf[g][s][0] = h2u32(w16eff(Whh, Wih, n, k0),
                                w16eff(Whh, Wih, n, k0 + 1));
            Bf[g][s][1] = h2u32(w16eff(Whh, Wih, n, k0 + 8),
                                w16eff(Whh, Wih, n, k0 + 9));
        }
    }
    float bg[4][2];
    #pragma unroll
    for (int g = 0; g < 4; g++) {
        int n = 32 * g + j0;
        bg[g][0] = bih[n]     + bhh[n];
        bg[g][1] = bih[n + 1] + bhh[n + 1];
    }

    // ---- projection fragments (warps 0..2), live k-steps {0,1,2,3,8,9} ----
    u32 Bp[6][2];
    float bp0 = 0.f, bp1 = 0.f;
    const int mc = j0;
    if (warp < 3) {
        int m = 8 * warp + gr;
        const int lives[6] = {0, 1, 2, 3, 8, 9};
        #pragma unroll
        for (int i = 0; i < 6; i++) {
            int k0 = 16 * lives[i] + 2 * tc;
            Bp[i][0] = h2u32(wout_eff(Wout, m, k0),     wout_eff(Wout, m, k0 + 1));
            Bp[i][1] = h2u32(wout_eff(Wout, m, k0 + 8), wout_eff(Wout, m, k0 + 9));
        }
        if (mc < NL) { bp0 = bout[mc]; bp1 = bout[mc + 1]; }
    }

    // ---- zero both A buffers ----
    for (int i = tid; i < 2 * 16 * (ASTR / 2); i += 128)
        ((u32*)As)[i] = 0u;
    __syncthreads();

    // z staging: 144 slots (16 rows x 9 pairs) over 128 threads -> 2 slots.
    // slot0: idx=tid (always valid); slot1: idx=tid+128 (valid for tid<16).
    const int  zr0 = tid / 9,           zc0 = 2 * (tid % 9);
    const int  zr1 = (tid + 128) / 9,   zc1 = 2 * ((tid + 128) % 9);
    const bool zv1 = (tid + 128) < 144;

    float2 zn0 = make_float2(0.f, 0.f), zn1 = make_float2(0.f, 0.f);
    {
        float2 v = *(const float2*)(z + ((size_t)(be + zr0) * NT + 0) * NL + zc0);
        __half2 z16 = __floats2half2_rn(v.x, v.y);
        float2 zb = __half22float2(z16);
        __half2 zr = __floats2half2_rn(v.x - zb.x, v.y - zb.y);
        *(__half2*)&As[0][zr0][64 + zc0]  = z16;
        *(__half2*)&As[0][zr0][160 + zc0] = z16;
        *(__half2*)&As[0][zr0][96 + zc0]  = zr;
        zn0 = *(const float2*)(z + ((size_t)(be + zr0) * NT + 1) * NL + zc0);
    }
    if (zv1) {
        float2 v = *(const float2*)(z + ((size_t)(be + zr1) * NT + 0) * NL + zc1);
        __half2 z16 = __floats2half2_rn(v.x, v.y);
        float2 zb = __half22float2(z16);
        __half2 zr = __floats2half2_rn(v.x - zb.x, v.y - zb.y);
        *(__half2*)&As[0][zr1][64 + zc1]  = z16;
        *(__half2*)&As[0][zr1][160 + zc1] = z16;
        *(__half2*)&As[0][zr1][96 + zc1]  = zr;
        zn1 = *(const float2*)(z + ((size_t)(be + zr1) * NT + 1) * NL + zc1);
    }
    __syncthreads();

    // states: q=0 (row gr, j0), q=1 (gr, j0+1), q=2 (gr+8, j0), q=3 (gr+8, j0+1)
    float cst[4] = {0.f, 0.f, 0.f, 0.f};
    float hv[4]  = {0.f, 0.f, 0.f, 0.f};

    for (int t = 0; t <= NT; t++) {
        const __half (*Ab)[ASTR] = As[t & 1];

        float d[4][4];
        #pragma unroll
        for (int g = 0; g < 4; g++) {
            d[g][0] = bg[g][0]; d[g][1] = bg[g][1];
            d[g][2] = bg[g][0]; d[g][3] = bg[g][1];
        }
        float dp[4] = {bp0, bp1, bp0, bp1};

        #pragma unroll
        for (int s = 0; s < KS; s++) {
            u32 a[4];
            int k0 = 16 * s + 2 * tc;
            a[0] = *(const u32*)&Ab[gr][k0];
            a[1] = *(const u32*)&Ab[gr + 8][k0];
            a[2] = *(const u32*)&Ab[gr][k0 + 8];
            a[3] = *(const u32*)&Ab[gr + 8][k0 + 8];
            mma16816(d[0], a, Bf[0][s]);
            mma16816(d[1], a, Bf[1][s]);
            mma16816(d[2], a, Bf[2][s]);
            mma16816(d[3], a, Bf[3][s]);
            if (warp < 3) {
                if (s < 4)       mma16816(dp, a, Bp[s]);
                else if (s == 8) mma16816(dp, a, Bp[4]);
                else if (s == 9) mma16816(dp, a, Bp[5]);
            }
        }

        // z_pred[t-1] straight from proj accumulators
        if (t >= 1 && warp < 3 && mc < NL) {
            *(float2*)(out + ((size_t)(be + gr)     * NT + (t - 1)) * NL + mc) =
                make_float2(dp[0], dp[1]);
            *(float2*)(out + ((size_t)(be + gr + 8) * NT + (t - 1)) * NL + mc) =
                make_float2(dp[2], dp[3]);
        }

        if (t < NT) {
            __half (*An)[ASTR] = As[(t + 1) & 1];

            // register pointwise: thread owns full gate quadruples
            #pragma unroll
            for (int q = 0; q < 4; q++) {
                float ii = sigmoid_fast(d[0][q]);
                float ff = sigmoid_fast(d[1][q]);
                float g2 = tanh_fast(d[2][q]);
                float oo = sigmoid_fast(d[3][q]);
                cst[q] = ff * cst[q] + ii * g2;
                hv[q] = oo * tanh_fast(cst[q]);
            }

            // h -> fp16 + residual into next A buffer (rows gr, gr+8)
            {
                __half2 h16 = __floats2half2_rn(hv[0], hv[1]);
                float2 hb = __half22float2(h16);
                __half2 hr = __floats2half2_rn(hv[0] - hb.x, hv[1] - hb.y);
                *(__half2*)&An[gr][0   + j0] = h16;
                *(__half2*)&An[gr][128 + j0] = h16;
                *(__half2*)&An[gr][32  + j0] = hr;
            }
            {
                __half2 h16 = __floats2half2_rn(hv[2], hv[3]);
                float2 hb = __half22float2(h16);
                __half2 hr = __floats2half2_rn(hv[2] - hb.x, hv[3] - hb.y);
                *(__half2*)&An[gr + 8][0   + j0] = h16;
                *(__half2*)&An[gr + 8][128 + j0] = h16;
                *(__half2*)&An[gr + 8][32  + j0] = hr;
            }

            // stage z(t+1) into next buffer (both slots), prefetch z(t+2)
            if (t + 1 < NT) {
                {
                    __half2 z16 = __floats2half2_rn(zn0.x, zn0.y);
                    float2 zb = __half22float2(z16);
                    __half2 zr = __floats2half2_rn(zn0.x - zb.x, zn0.y - zb.y);
                    *(__half2*)&An[zr0][64 + zc0]  = z16;
                    *(__half2*)&An[zr0][160 + zc0] = z16;
                    *(__half2*)&An[zr0][96 + zc0]  = zr;
                    if (t + 2 < NT)
                        zn0 = *(const float2*)(z + ((size_t)(be + zr0) * NT + t + 2) * NL + zc0);
                }
                if (zv1) {
                    __half2 z16 = __floats2half2_rn(zn1.x, zn1.y);
                    float2 zb = __half22float2(z16);
                    __half2 zr = __floats2half2_rn(zn1.x - zb.x, zn1.y - zb.y);
                    *(__half2*)&An[zr1][64 + zc1]  = z16;
                    *(__half2*)&An[zr1][160 + zc1] = z16;
                    *(__half2*)&An[zr1][96 + zc1]  = zr;
                    if (t + 2 < NT)
                        zn1 = *(const float2*)(z + ((size_t)(be + zr1) * NT + t + 2) * NL + zc1);
                }
            }
        }
        __syncthreads();   // the ONLY barrier per step
    }

    // out layout: [z_pred (B*T*18) | h_n (B*32) | c_n (B*32)]
    float* hOut = out + (size_t)NB * NT * NL;
    float* cOut = hOut + (size_t)NB * NH;
    *(float2*)&hOut[(size_t)(be + gr)     * NH + j0] = make_float2(hv[0], hv[1]);
    *(float2*)&hOut[(size_t)(be + gr + 8) * NH + j0] = make_float2(hv[2], hv[3]);
    *(float2*)&cOut[(size_t)(be + gr)     * NH + j0] = make_float2(cst[0], cst[1]);
    *(float2*)&cOut[(size_t)(be + gr + 8) * NH + j0] = make_float2(cst[2], cst[3]);
}

extern "C" void kernel_launch(void* const* d_in, const int* in_sizes, int n_in,
                              void* d_out, int out_size)
{
    const float* z    = (const float*)d_in[0];
    const float* Wih  = (const float*)d_in[1];
    const float* Whh  = (const float*)d_in[2];
    const float* bih  = (const float*)d_in[3];
    const float* bhh  = (const float*)d_in[4];
    const float* Wout = (const float*)d_in[5];
    const float* bout = (const float*)d_in[6];
    float* out = (float*)d_out;

    lstm_fused_tc<<<NB / 16, 128>>>(z, Wih, Whh, bih, bhh, Wout, bout, out);
}

// round 14
// speedup vs baseline: 1.1902x; 1.1902x over previous
#include <cuda_runtime.h>
#include <cuda_fp16.h>

// LSTM B=2048, T=512, LATENT=18, HID=32, gates (i,f,g,o), 4H=128.
// R14: split-gate warp pairing. 128 blocks x 256 threads (8 warps, 2/SMSP).
// Warp w (0-3) owns gate tiles i,g for hidden slice cols 8w..8w+7; warp w+4
// owns f,o for the same slice (+ proj tiles on warps 4-6). MMA -> warps 4-7
// STS f,o to Cs -> bar -> warps 0-3 pointwise (i,g in regs; f,o via LDS)
// while warps 4-7 stage z(t+1) -> bar. Single A buffer. z_pred stored
// directly from warp 4-6 proj accumulators. Residual-split fp16 numerics
// (validated rel_err ~3.6e-7 in R10/R11/R13).

#define NB 2048
#define NT 512
#define NL 18
#define NH 32
#define KS 12          // k-steps of 16 (K=192)
#define ASTR 200       // half stride of A rows
#define CSTR 136       // float stride of Cs rows

typedef unsigned int u32;

__device__ __forceinline__ float ex2(float x) {
    float r; asm("ex2.approx.f32 %0,%1;" : "=f"(r) : "f"(x)); return r;
}
__device__ __forceinline__ float rcpa(float x) {
    float r; asm("rcp.approx.f32 %0,%1;" : "=f"(r) : "f"(x)); return r;
}
__device__ __forceinline__ float sigmoid_fast(float x) {
    return rcpa(1.0f + ex2(-1.4426950408889634f * x));
}
__device__ __forceinline__ float tanh_fast(float x) {
    return 1.0f - 2.0f * rcpa(ex2(2.8853900817779268f * x) + 1.0f);
}

__device__ __forceinline__ u32 h2u32(__half a, __half b) {
    __half2 hv = __halves2half2(a, b);
    return *reinterpret_cast<u32*>(&hv);
}

__device__ __forceinline__ void mma16816(float d[4], const u32 a[4], const u32 b[2]) {
    asm volatile(
        "mma.sync.aligned.m16n8k16.row.col.f32.f16.f16.f32 "
        "{%0,%1,%2,%3}, {%4,%5,%6,%7}, {%8,%9}, {%0,%1,%2,%3};"
        : "+f"(d[0]), "+f"(d[1]), "+f"(d[2]), "+f"(d[3])
        : "r"(a[0]), "r"(a[1]), "r"(a[2]), "r"(a[3]), "r"(b[0]), "r"(b[1]));
}

// Gate B_eff[kk][n], n = gate row 0..127 (main part kk<128, residual kk>=128)
__device__ __forceinline__ __half w16eff(const float* Whh, const float* Wih,
                                         int n, int kk) {
    float w;
    bool res = false;
    if (kk < 32)        w = Whh[n * NH + kk];
    else if (kk < 64)   w = Whh[n * NH + (kk - 32)];
    else if (kk < 96)   { int c = kk - 64; w = (c < NL) ? Wih[n * NL + c] : 0.f; }
    else if (kk < 128)  { int c = kk - 96; w = (c < NL) ? Wih[n * NL + c] : 0.f; }
    else if (kk < 160)  { w = Whh[n * NH + (kk - 128)]; res = true; }
    else                { int c = kk - 160; w = (c < NL) ? Wih[n * NL + c] : 0.f; res = true; }
    __half h = __float2half_rn(w);
    if (!res) return h;
    return __float2half_rn(w - __half2float(h));
}

// Projection B_eff[kk][m]: kk0-31 Wout16 (vs h16), kk32-63 Wout16 (vs hr),
// kk128-159 Wres (vs h16), else 0.
__device__ __forceinline__ __half wout_eff(const float* Wout, int m, int kk) {
    if (m >= NL) return __float2half_rn(0.f);
    float w; bool res = false;
    if (kk < 32)        w = Wout[m * NH + kk];
    else if (kk < 64)   w = Wout[m * NH + (kk - 32)];
    else if (kk < 128)  return __float2half_rn(0.f);
    else if (kk < 160)  { w = Wout[m * NH + (kk - 128)]; res = true; }
    else                return __float2half_rn(0.f);
    __half h = __float2half_rn(w);
    if (!res) return h;
    return __float2half_rn(w - __half2float(h));
}

__global__ __launch_bounds__(256, 1)
void lstm_fused_tc(const float* __restrict__ z,
                   const float* __restrict__ Wih,
                   const float* __restrict__ Whh,
                   const float* __restrict__ bih,
                   const float* __restrict__ bhh,
                   const float* __restrict__ Wout,
                   const float* __restrict__ bout,
                   float* __restrict__ out)
{
    // single A buffer: kk 0-31 h16, 32-63 hr, 64-95 z16, 96-127 zr,
    //                  128-159 h16, 160-191 z16
    __shared__ __half As[16][ASTR];
    __shared__ float  Cs[16][CSTR];   // only cols 32-63 (f) and 96-127 (o) used

    const int tid  = threadIdx.x;
    const int warp = tid >> 5;        // 0..7
    const int lane = tid & 31;
    const int gr   = lane >> 2;       // 0..7
    const int tc   = lane & 3;        // 0..3
    const int be   = blockIdx.x * 16;
    const int ws   = warp & 3;        // hidden-slice index 0..3
    const int j0   = 8 * ws + 2 * tc; // hidden pair for this slice
    const bool loW = warp < 4;        // i,g + pointwise warps

    // ---- B fragments: 2 gate tiles per warp ----
    // warps 0-3: gates 0 (i), 2 (g); warps 4-7: gates 1 (f), 3 (o)
    u32 Bf[2][KS][2];
    {
        int g0 = loW ? 0 : 1;
        int g1 = loW ? 2 : 3;
        int n0 = 32 * g0 + 8 * ws + gr;
        int n1 = 32 * g1 + 8 * ws + gr;
        #pragma unroll
        for (int s = 0; s < KS; s++) {
            int k0 = 16 * s + 2 * tc;
            Bf[0][s][0] = h2u32(w16eff(Whh, Wih, n0, k0),
                                w16eff(Whh, Wih, n0, k0 + 1));
            Bf[0][s][1] = h2u32(w16eff(Whh, Wih, n0, k0 + 8),
                                w16eff(Whh, Wih, n0, k0 + 9));
            Bf[1][s][0] = h2u32(w16eff(Whh, Wih, n1, k0),
                                w16eff(Whh, Wih, n1, k0 + 1));
            Bf[1][s][1] = h2u32(w16eff(Whh, Wih, n1, k0 + 8),
                                w16eff(Whh, Wih, n1, k0 + 9));
        }
    }
    float bb[2][2];   // biases for my two tiles' columns
    {
        int g0 = loW ? 0 : 1;
        int g1 = loW ? 2 : 3;
        bb[0][0] = bih[32 * g0 + j0]     + bhh[32 * g0 + j0];
        bb[0][1] = bih[32 * g0 + j0 + 1] + bhh[32 * g0 + j0 + 1];
        bb[1][0] = bih[32 * g1 + j0]     + bhh[32 * g1 + j0];
        bb[1][1] = bih[32 * g1 + j0 + 1] + bhh[32 * g1 + j0 + 1];
    }

    // ---- projection fragments (warps 4..6), live k-steps {0,1,2,3,8,9} ----
    u32 Bp[6][2];
    float bp0 = 0.f, bp1 = 0.f;
    const int wp = warp - 4;          // proj tile index (warps 4-6)
    const int mc = (wp >= 0) ? 8 * wp + 2 * tc : 0;
    const bool doProj = (!loW) && wp < 3 && mc < NL;
    if (!loW && wp < 3) {
        int m = 8 * wp + gr;
        const int lives[6] = {0, 1, 2, 3, 8, 9};
        #pragma unroll
        for (int i = 0; i < 6; i++) {
            int k0 = 16 * lives[i] + 2 * tc;
            Bp[i][0] = h2u32(wout_eff(Wout, m, k0),     wout_eff(Wout, m, k0 + 1));
            Bp[i][1] = h2u32(wout_eff(Wout, m, k0 + 8), wout_eff(Wout, m, k0 + 9));
        }
        if (mc < NL) { bp0 = bout[mc]; bp1 = bout[mc + 1]; }
    }

    // ---- zero A buffer (h=0 initial state) ----
    for (int i = tid; i < 16 * (ASTR / 2); i += 256)
        ((u32*)As)[i] = 0u;
    __syncthreads();

    // z staging on warps 4-7 (stid 0..127): slots stid and stid+128 (<144)
    const int  stid = tid - 128;
    const int  zr0 = (stid >= 0) ? stid / 9 : 0;
    const int  zc0 = (stid >= 0) ? 2 * (stid % 9) : 0;
    const int  zr1 = (stid >= 0) ? (stid + 128) / 9 : 0;
    const int  zc1 = (stid >= 0) ? 2 * ((stid + 128) % 9) : 0;
    const bool zv0 = stid >= 0;
    const bool zv1 = stid >= 0 && (stid + 128) < 144;

    float2 zn0 = make_float2(0.f, 0.f), zn1 = make_float2(0.f, 0.f);
    if (zv0) {
        float2 v = *(const float2*)(z + ((size_t)(be + zr0) * NT + 0) * NL + zc0);
        __half2 z16 = __floats2half2_rn(v.x, v.y);
        float2 zb = __half22float2(z16);
        __half2 zr = __floats2half2_rn(v.x - zb.x, v.y - zb.y);
        *(__half2*)&As[zr0][64 + zc0]  = z16;
        *(__half2*)&As[zr0][160 + zc0] = z16;
        *(__half2*)&As[zr0][96 + zc0]  = zr;
        zn0 = *(const float2*)(z + ((size_t)(be + zr0) * NT + 1) * NL + zc0);
    }
    if (zv1) {
        float2 v = *(const float2*)(z + ((size_t)(be + zr1) * NT + 0) * NL + zc1);
        __half2 z16 = __floats2half2_rn(v.x, v.y);
        float2 zb = __half22float2(z16);
        __half2 zr = __floats2half2_rn(v.x - zb.x, v.y - zb.y);
        *(__half2*)&As[zr1][64 + zc1]  = z16;
        *(__half2*)&As[zr1][160 + zc1] = z16;
        *(__half2*)&As[zr1][96 + zc1]  = zr;
        zn1 = *(const float2*)(z + ((size_t)(be + zr1) * NT + 1) * NL + zc1);
    }
    __syncthreads();

    // states (warps 0-3): q0=(gr,j0) q1=(gr,j0+1) q2=(gr+8,j0) q3=(gr+8,j0+1)
    float cst[4] = {0.f, 0.f, 0.f, 0.f};
    float hv[4]  = {0.f, 0.f, 0.f, 0.f};

    for (int t = 0; t <= NT; t++) {
        // ---- phase 1: MMA (everyone reads As; all reads precede bar1) ----
        float d0[4] = {bb[0][0], bb[0][1], bb[0][0], bb[0][1]};
        float d1[4] = {bb[1][0], bb[1][1], bb[1][0], bb[1][1]};
        float dp[4] = {bp0, bp1, bp0, bp1};

        #pragma unroll
        for (int s = 0; s < KS; s++) {
            u32 a[4];
            int k0 = 16 * s + 2 * tc;
            a[0] = *(const u32*)&As[gr][k0];
            a[1] = *(const u32*)&As[gr + 8][k0];
            a[2] = *(const u32*)&As[gr][k0 + 8];
            a[3] = *(const u32*)&As[gr + 8][k0 + 8];
            mma16816(d0, a, Bf[0][s]);
            mma16816(d1, a, Bf[1][s]);
            if (!loW && wp < 3) {
                if (s < 4)       mma16816(dp, a, Bp[s]);
                else if (s == 8) mma16816(dp, a, Bp[4]);
                else if (s == 9) mma16816(dp, a, Bp[5]);
            }
        }

        // warps 4-7: publish f,o to Cs; warps 4-6: store z_pred[t-1]
        if (!loW) {
            *(float2*)&Cs[gr][32 + j0]     = make_float2(d0[0], d0[1]);
            *(float2*)&Cs[gr + 8][32 + j0] = make_float2(d0[2], d0[3]);
            *(float2*)&Cs[gr][96 + j0]     = make_float2(d1[0], d1[1]);
            *(float2*)&Cs[gr + 8][96 + j0] = make_float2(d1[2], d1[3]);
            if (t >= 1 && doProj) {
                *(float2*)(out + ((size_t)(be + gr)     * NT + (t - 1)) * NL + mc) =
                    make_float2(dp[0], dp[1]);
                *(float2*)(out + ((size_t)(be + gr + 8) * NT + (t - 1)) * NL + mc) =
                    make_float2(dp[2], dp[3]);
            }
        }
        __syncthreads();   // bar1: f,o visible; As reads complete

        if (t < NT) {
            if (loW) {
                // ---- pointwise: i,g from regs (d0,d1), f,o from Cs ----
                float2 f01 = *(const float2*)&Cs[gr][32 + j0];
                float2 f23 = *(const float2*)&Cs[gr + 8][32 + j0];
                float2 o01 = *(const float2*)&Cs[gr][96 + j0];
                float2 o23 = *(const float2*)&Cs[gr + 8][96 + j0];
                float fq[4] = {f01.x, f01.y, f23.x, f23.y};
                float oq[4] = {o01.x, o01.y, o23.x, o23.y};

                #pragma unroll
                for (int q = 0; q < 4; q++) {
                    float ii = sigmoid_fast(d0[q]);
                    float g2 = tanh_fast(d1[q]);
                    float ff = sigmoid_fast(fq[q]);
                    float oo = sigmoid_fast(oq[q]);
                    cst[q] = ff * cst[q] + ii * g2;
                    hv[q] = oo * tanh_fast(cst[q]);
                }

                // h -> fp16 + residual into A (rows gr, gr+8)
                {
                    __half2 h16 = __floats2half2_rn(hv[0], hv[1]);
                    float2 hb = __half22float2(h16);
                    __half2 hr = __floats2half2_rn(hv[0] - hb.x, hv[1] - hb.y);
                    *(__half2*)&As[gr][0   + j0] = h16;
                    *(__half2*)&As[gr][128 + j0] = h16;
                    *(__half2*)&As[gr][32  + j0] = hr;
                }
                {
                    __half2 h16 = __floats2half2_rn(hv[2], hv[3]);
                    float2 hb = __half22float2(h16);
                    __half2 hr = __floats2half2_rn(hv[2] - hb.x, hv[3] - hb.y);
                    *(__half2*)&As[gr + 8][0   + j0] = h16;
                    *(__half2*)&As[gr + 8][128 + j0] = h16;
                    *(__half2*)&As[gr + 8][32  + j0] = hr;
                }
            } else if (t + 1 < NT) {
                // ---- warps 4-7: stage z(t+1) into A, prefetch z(t+2) ----
                if (zv0) {
                    __half2 z16 = __floats2half2_rn(zn0.x, zn0.y);
                    float2 zb = __half22float2(z16);
                    __half2 zr = __floats2half2_rn(zn0.x - zb.x, zn0.y - zb.y);
                    *(__half2*)&As[zr0][64 + zc0]  = z16;
                    *(__half2*)&As[zr0][160 + zc0] = z16;
                    *(__half2*)&As[zr0][96 + zc0]  = zr;
                    if (t + 2 < NT)
                        zn0 = *(const float2*)(z + ((size_t)(be + zr0) * NT + t + 2) * NL + zc0);
                }
                if (zv1) {
                    __half2 z16 = __floats2half2_rn(zn1.x, zn1.y);
                    float2 zb = __half22float2(z16);
                    __half2 zr = __floats2half2_rn(zn1.x - zb.x, zn1.y - zb.y);
                    *(__half2*)&As[zr1][64 + zc1]  = z16;
                    *(__half2*)&As[zr1][160 + zc1] = z16;
                    *(__half2*)&As[zr1][96 + zc1]  = zr;
                    if (t + 2 < NT)
                        zn1 = *(const float2*)(z + ((size_t)(be + zr1) * NT + t + 2) * NL + zc1);
                }
            }
        }
        __syncthreads();   // bar2: h and z(t+1) visible for next MMA
    }

    // out layout: [z_pred (B*T*18) | h_n (B*32) | c_n (B*32)]
    if (loW) {
        float* hOut = out + (size_t)NB * NT * NL;
        float* cOut = hOut + (size_t)NB * NH;
        *(float2*)&hOut[(size_t)(be + gr)     * NH + j0] = make_float2(hv[0], hv[1]);
        *(float2*)&hOut[(size_t)(be + gr + 8) * NH + j0] = make_float2(hv[2], hv[3]);
        *(float2*)&cOut[(size_t)(be + gr)     * NH + j0] = make_float2(cst[0], cst[1]);
        *(float2*)&cOut[(size_t)(be + gr + 8) * NH + j0] = make_float2(cst[2], cst[3]);
    }
}

extern "C" void kernel_launch(void* const* d_in, const int* in_sizes, int n_in,
                              void* d_out, int out_size)
{
    const float* z    = (const float*)d_in[0];
    const float* Wih  = (const float*)d_in[1];
    const float* Whh  = (const float*)d_in[2];
    const float* bih  = (const float*)d_in[3];
    const float* bhh  = (const float*)d_in[4];
    const float* Wout = (const float*)d_in[5];
    const float* bout = (const float*)d_in[6];
    float* out = (float*)d_out;

    lstm_fused_tc<<<NB / 16, 256>>>(z, Wih, Whh, bih, bhh, Wout, bout, out);
}